// round 10
// baseline (speedup 1.0000x reference)
#include <cuda_runtime.h>
#include <math.h>

#define IN_F   1024
#define OUT_F  512
#define BATCH  256
#define NBLK   512
#define CAP    96
#define TLO    0.02f
#define THI    0.98f

// Transposed no_edge bit matrix: [i][o_word], bit = o&31. 64 KB.
__device__ unsigned g_maskT[IN_F * (OUT_F / 32)];
// Monotonic arrival counter (never reset; each launch adds exactly NBLK).
__device__ unsigned g_done;

// ---------------------------------------------------------------------------
// no_edge = argmax(etc + gumbel(u)) == 1, i.e. (etc1+g1) > (etc0+g0) strictly
// (argmax tie -> index 0). g(u) = -log(-log(u+eps)+eps) is strictly
// increasing, so for etc0==etc1 this is exactly u1>u0; full gumbel math as
// the general fallback.
// ---------------------------------------------------------------------------
__device__ __forceinline__ bool no_edge_of(float e0, float e1, float u0, float u1) {
    if (e0 == e1) return u1 > u0;
    const float eps = 1e-10f;
    float g0 = -logf(-logf(u0 + eps) + eps);
    float g1 = -logf(-logf(u1 + eps) + eps);
    return (e1 + g1) > (e0 + g0);
}

// ---------------------------------------------------------------------------
// Fused kernel, grid = 512 blocks x 256 threads, ALL blocks co-resident
// (launch_bounds(256,4): regs<=64, smem ~15KB -> >=4 blocks/SM -> 592 slots).
//
// Phase A (block bid): build mask tile ow=bid&15, iw=bid>>4 (32o x 32i),
//   ballot-transpose, store 32 maskT words. Fence + arrive on g_done.
// Phase E (overlapped, no mask dependency): block (b=bid>>1, par=bid&1)
//   loads x row, extracts candidates (v<TLO min side / v>THI max side).
// Spin until all NBLK arrivals of THIS launch (monotonic target).
// Phase S: stage candidate mask rows to smem, scan: thread t -> output
//   o = 2t+par; candidate accepted if its no_edge bit for o is clear.
// Deterministic full-scan fallback (no unmasked candidate / overflow).
// Clamp to identity offsets (2 / -1) handles all-no-edge rows exactly.
// ---------------------------------------------------------------------------
__global__ __launch_bounds__(256, 4)
void fused_kernel(const float* __restrict__ etc, const float* __restrict__ un,
                  const float* __restrict__ x, float* __restrict__ out) {
    __shared__ unsigned bits[32][33];    // phase A transpose staging
    __shared__ float    xsh[IN_F];
    __shared__ float    cv[CAP];
    __shared__ int      ci[CAP];
    __shared__ unsigned cm[CAP][16];
    __shared__ int      n_s;
    __shared__ unsigned tgt_s;

    const int t    = threadIdx.x;
    const int lane = t & 31;
    const int w    = t >> 5;
    const int bid  = blockIdx.x;

    // ---------------- Phase A: mask tile ----------------
    {
        const int ow = bid & 15;         // o-word index (OUT_F/32)
        const int iw = bid >> 4;         // i-tile index (IN_F/32)
        const int o_local = t >> 3;
        const int i_local = (t & 7) << 2;
        const size_t gp = (size_t)(ow * 32 + o_local) * IN_F + (iw * 32 + i_local);
        const size_t f0 = gp >> 1;       // float4 index (2 pairs per float4)

        float4 ea = ((const float4*)etc)[f0];
        float4 eb = ((const float4*)etc)[f0 + 1];
        float4 ua = ((const float4*)un)[f0];
        float4 ub = ((const float4*)un)[f0 + 1];

        bits[i_local + 0][o_local] = no_edge_of(ea.x, ea.y, ua.x, ua.y) ? 1u : 0u;
        bits[i_local + 1][o_local] = no_edge_of(ea.z, ea.w, ua.z, ua.w) ? 1u : 0u;
        bits[i_local + 2][o_local] = no_edge_of(eb.x, eb.y, ub.x, ub.y) ? 1u : 0u;
        bits[i_local + 3][o_local] = no_edge_of(eb.z, eb.w, ub.z, ub.w) ? 1u : 0u;

        __syncthreads();

        #pragma unroll
        for (int r = 0; r < 4; r++) {
            const int i = (w << 2) + r;
            unsigned word = __ballot_sync(0xFFFFFFFFu, bits[i][lane] != 0u);
            if (lane == 0) g_maskT[(size_t)(iw * 32 + i) * 16 + ow] = word;
        }
        __syncthreads();            // all stores issued before fence/arrive
        if (t == 0) {
            __threadfence();        // release our maskT stores
            unsigned r = atomicAdd(&g_done, 1u);
            tgt_s = (r / NBLK + 1u) * NBLK;   // completion count of THIS launch
            n_s = 0;
        }
    }
    __syncthreads();

    // ---------------- Phase E: extraction (mask-independent) ----------------
    const int b   = bid >> 1;
    const int par = bid & 1;             // 0 = min side, 1 = max side

    float4 v4 = ((const float4*)(x + (size_t)b * IN_F))[t];
    ((float4*)xsh)[t] = v4;
    float vals[4] = {v4.x, v4.y, v4.z, v4.w};
    #pragma unroll
    for (int j = 0; j < 4; j++) {
        float v = vals[j];
        bool  c = par ? (v > THI) : (v < TLO);
        unsigned m = __ballot_sync(0xFFFFFFFFu, c);
        if (c) {
            int rank = __popc(m & ((1u << lane) - 1u));
            int base = 0;
            int lead = __ffs(m) - 1;
            if (lane == lead) base = atomicAdd(&n_s, __popc(m));
            base = __shfl_sync(m, base, lead);
            int p = base + rank;
            if (p < CAP) { cv[p] = v; ci[p] = 4 * t + j; }
        }
    }
    __syncthreads();

    // ---------------- Grid barrier: wait for all mask tiles ----------------
    if (t == 0) {
        const unsigned target = tgt_s;
        while (*(volatile unsigned*)&g_done < target) { __nanosleep(64); }
        __threadfence();            // acquire all maskT stores
    }
    __syncthreads();

    // ---------------- Phase S: stage candidate masks + scan ----------------
    const int  n   = min(n_s, CAP);
    const bool ovf = (n_s > CAP);

    for (int k = t; k < n * 16; k += 256) {
        int c = k >> 4;
        cm[c][k & 15] = __ldg(&g_maskT[(size_t)ci[c] * 16 + (k & 15)]);
    }
    __syncthreads();

    const int o  = 2 * t + par;
    const int wo = o >> 5, bo = o & 31;
    const float INF  = __int_as_float(0x7F800000);
    const float NINF = __int_as_float(0xFF800000);
    const float init = par ? NINF : INF;

    float acc = init;
    if (!ovf) {
        if (par) {
            #pragma unroll 8
            for (int c = 0; c < n; c++) {
                unsigned wd = cm[c][wo];
                if (!((wd >> bo) & 1u)) acc = fmaxf(acc, cv[c]);
            }
        } else {
            #pragma unroll 8
            for (int c = 0; c < n; c++) {
                unsigned wd = cm[c][wo];
                if (!((wd >> bo) & 1u)) acc = fminf(acc, cv[c]);
            }
        }
    }
    if (acc == init) {   // no unmasked candidate (or overflow): full scan
        const unsigned* __restrict__ mt = g_maskT;
        if (par) {
            for (int i = 0; i < IN_F; i++) {
                unsigned wd = __ldg(&mt[(size_t)i * 16 + wo]);
                if (!((wd >> bo) & 1u)) acc = fmaxf(acc, xsh[i]);
            }
        } else {
            for (int i = 0; i < IN_F; i++) {
                unsigned wd = __ldg(&mt[(size_t)i * 16 + wo]);
                if (!((wd >> bo) & 1u)) acc = fminf(acc, xsh[i]);
            }
        }
    }

    float r = par ? fmaxf(acc, -1.0f) : fminf(acc, 2.0f);
    out[(size_t)b * OUT_F + o] = r;
}

extern "C" void kernel_launch(void* const* d_in, const int* in_sizes, int n_in,
                              void* d_out, int out_size) {
    const float* x   = (const float*)d_in[0];  // [256, 1024]
    const float* etc = (const float*)d_in[1];  // [512, 1024, 2]
    const float* un  = (const float*)d_in[2];  // [512, 1024, 2]
    float* out = (float*)d_out;                // [256, 512]

    fused_kernel<<<NBLK, 256>>>(etc, un, x, out);
}